// round 6
// baseline (speedup 1.0000x reference)
#include <cuda_runtime.h>
#include <mma.h>
#include <math.h>

using namespace nvcuda;

#define NUM_E 8
#define BATCH 4096
#define DIM   1024
#define DHID  4096

// --- device scratch (no allocations allowed) ---
__device__ int   g_cnt[NUM_E];
__device__ int   g_cur[NUM_E];
__device__ int   g_off[NUM_E + 1];
__device__ int   g_perm[BATCH];
__device__ float g_hid[(size_t)BATCH * DHID];   // 64 MB, permuted-row order

// ---------------- routing ----------------
__global__ void k_zero() {
    int i = threadIdx.x;
    if (i < NUM_E) { g_cnt[i] = 0; g_cur[i] = 0; }
}

__device__ __forceinline__ int expert_of(float t) {
    int e = (int)(t * 8.0f);           // t / H_STEP, H_STEP = 1/8 exact
    if (e < 0) e = 0;
    if (e > NUM_E - 1) e = NUM_E - 1;
    return e;
}

__global__ void k_hist(const float* __restrict__ t) {
    int i = blockIdx.x * blockDim.x + threadIdx.x;
    if (i < BATCH) atomicAdd(&g_cnt[expert_of(t[i])], 1);
}

__global__ void k_scan() {
    if (threadIdx.x == 0) {
        int s = 0;
        for (int e = 0; e < NUM_E; e++) { g_off[e] = s; s += g_cnt[e]; }
        g_off[NUM_E] = s;
    }
}

__global__ void k_scatter(const float* __restrict__ t) {
    int i = blockIdx.x * blockDim.x + threadIdx.x;
    if (i < BATCH) {
        int e = expert_of(t[i]);
        int p = atomicAdd(&g_cur[e], 1);
        g_perm[g_off[e] + p] = i;
    }
}

__device__ __forceinline__ float sigmoidf_(float x) { return 1.0f / (1.0f + expf(-x)); }

// ---------------- tf32 WMMA tiles: 128x128x32, 8 warps, warp = 64x32 ----------------
// AS_STRIDE / BS_STRIDE multiples of 8 floats (32B alignment for load_matrix_sync)
#define AS_STRIDE 40
#define BS_STRIDE 136

// frag types
typedef wmma::fragment<wmma::matrix_a, 16, 16, 8, wmma::precision::tf32, wmma::row_major> FragA;
typedef wmma::fragment<wmma::matrix_b, 16, 16, 8, wmma::precision::tf32, wmma::row_major> FragB;
typedef wmma::fragment<wmma::accumulator, 16, 16, 8, float> FragC;

// GEMM1: hid[seg0+m][n] = tanh( y[perm[seg0+m]][:] . W1[e][:, n] + b1[e][n] )
__global__ __launch_bounds__(256)
void k_gemm1(const float* __restrict__ y, const float* __restrict__ W1,
             const float* __restrict__ b1)
{
    const int e    = blockIdx.z;
    const int seg0 = g_off[e];
    const int cnt  = g_off[e + 1] - seg0;
    const int tm   = blockIdx.y;
    if (tm * 128 >= cnt) return;
    const int tn = blockIdx.x;

    __shared__ float As[128 * AS_STRIDE];   // [row][k]  20 KB
    __shared__ float Bs[32 * BS_STRIDE];    // [k][n]    17 KB
    __shared__ float Cs[8 * 256];           // per-warp 16x16   8 KB

    const int tid  = threadIdx.x;
    const int wid  = tid >> 5;
    const int lane = tid & 31;
    const int wm   = wid >> 2;     // 0..1 (M)
    const int wn   = wid & 3;      // 0..3 (N)

    // Precompute A-loader coordinates (4 float4 slots / thread over 128x32 tile)
    int  srow[4]; int arow[4]; int ak4[4]; bool avalid[4];
#pragma unroll
    for (int i = 0; i < 4; i++) {
        int lin = tid + i * 256;        // 0..1023 float4 slots
        arow[i] = lin >> 3;             // 8 float4 per row of 32 floats
        ak4[i]  = (lin & 7) * 4;
        int gm  = tm * 128 + arow[i];
        avalid[i] = (gm < cnt);
        srow[i] = avalid[i] ? g_perm[seg0 + gm] : 0;
    }
    // B-loader coordinates (32 x 128 tile)
    int bk[4], bn4[4];
#pragma unroll
    for (int i = 0; i < 4; i++) {
        int lin = tid + i * 256;
        bk[i]  = lin >> 5;              // 32 float4 per row of 128 floats
        bn4[i] = (lin & 31) * 4;
    }
    const float* Wbase = W1 + (size_t)e * DIM * DHID + (size_t)tn * 128;

    FragC acc[4][2];
#pragma unroll
    for (int i = 0; i < 4; i++)
#pragma unroll
        for (int j = 0; j < 2; j++) wmma::fill_fragment(acc[i][j], 0.0f);

    const int nstage = DIM / 32;
    for (int kt = 0; kt < nstage; kt++) {
        const int k0 = kt * 32;
#pragma unroll
        for (int i = 0; i < 4; i++) {
            float4 v = avalid[i]
                ? *(const float4*)(y + (size_t)srow[i] * DIM + k0 + ak4[i])
                : make_float4(0.f, 0.f, 0.f, 0.f);
            *(float4*)&As[arow[i] * AS_STRIDE + ak4[i]] = v;
        }
#pragma unroll
        for (int i = 0; i < 4; i++) {
            float4 v = *(const float4*)(Wbase + (size_t)(k0 + bk[i]) * DHID + bn4[i]);
            *(float4*)&Bs[bk[i] * BS_STRIDE + bn4[i]] = v;
        }
        __syncthreads();

#pragma unroll
        for (int kk = 0; kk < 4; kk++) {
            FragA a[4];
            FragB b[2];
#pragma unroll
            for (int fm = 0; fm < 4; fm++) {
                wmma::load_matrix_sync(a[fm], &As[(wm * 64 + fm * 16) * AS_STRIDE + kk * 8], AS_STRIDE);
#pragma unroll
                for (int t = 0; t < a[fm].num_elements; t++)
                    a[fm].x[t] = wmma::__float_to_tf32(a[fm].x[t]);
            }
#pragma unroll
            for (int fn = 0; fn < 2; fn++) {
                wmma::load_matrix_sync(b[fn], &Bs[(kk * 8) * BS_STRIDE + wn * 32 + fn * 16], BS_STRIDE);
#pragma unroll
                for (int t = 0; t < b[fn].num_elements; t++)
                    b[fn].x[t] = wmma::__float_to_tf32(b[fn].x[t]);
            }
#pragma unroll
            for (int fm = 0; fm < 4; fm++)
#pragma unroll
                for (int fn = 0; fn < 2; fn++)
                    wmma::mma_sync(acc[fm][fn], a[fm], b[fn], acc[fm][fn]);
        }
        __syncthreads();
    }

    // epilogue: tanh(acc + b1) -> g_hid (permuted rows, contiguous)
    float* cbuf = &Cs[wid * 256];
    const float* b1e = b1 + (size_t)e * DHID;
#pragma unroll
    for (int fm = 0; fm < 4; fm++) {
#pragma unroll
        for (int fn = 0; fn < 2; fn++) {
            wmma::store_matrix_sync(cbuf, acc[fm][fn], 16, wmma::mem_row_major);
            __syncwarp();
#pragma unroll
            for (int j = 0; j < 8; j++) {
                int idx = lane + j * 32;          // 0..255
                int r = idx >> 4, c = idx & 15;
                int gm   = tm * 128 + wm * 64 + fm * 16 + r;
                int gcol = tn * 128 + wn * 32 + fn * 16 + c;
                if (gm < cnt)
                    g_hid[(size_t)(seg0 + gm) * DHID + gcol] = tanhf(cbuf[idx] + b1e[gcol]);
            }
            __syncwarp();
        }
    }
}

// GEMM2 + epilogue: out[perm[m]] = cf*sig(scales)*(hid.W2 + b2) + cy*y[perm[m]]
__global__ __launch_bounds__(256)
void k_gemm2(const float* __restrict__ y, const float* __restrict__ W2,
             const float* __restrict__ b2, const float* __restrict__ scales,
             const float* __restrict__ shifta, const float* __restrict__ shiftb,
             float* __restrict__ out)
{
    const int e    = blockIdx.z;
    const int seg0 = g_off[e];
    const int cnt  = g_off[e + 1] - seg0;
    const int tm   = blockIdx.y;
    if (tm * 128 >= cnt) return;
    const int tn = blockIdx.x;

    __shared__ float As[128 * AS_STRIDE];
    __shared__ float Bs[32 * BS_STRIDE];
    __shared__ float Cs[8 * 256];

    const int tid  = threadIdx.x;
    const int wid  = tid >> 5;
    const int lane = tid & 31;
    const int wm   = wid >> 2;
    const int wn   = wid & 3;

    int arow[4]; int ak4[4]; bool avalid[4]; const float* aptr[4];
#pragma unroll
    for (int i = 0; i < 4; i++) {
        int lin = tid + i * 256;
        arow[i] = lin >> 3;
        ak4[i]  = (lin & 7) * 4;
        int gm  = tm * 128 + arow[i];
        avalid[i] = (gm < cnt);
        aptr[i] = g_hid + (size_t)(seg0 + (avalid[i] ? gm : 0)) * DHID + ak4[i];
    }
    int bk[4], bn4[4];
#pragma unroll
    for (int i = 0; i < 4; i++) {
        int lin = tid + i * 256;
        bk[i]  = lin >> 5;
        bn4[i] = (lin & 31) * 4;
    }
    const float* Wbase = W2 + (size_t)e * DHID * DIM + (size_t)tn * 128;

    FragC acc[4][2];
#pragma unroll
    for (int i = 0; i < 4; i++)
#pragma unroll
        for (int j = 0; j < 2; j++) wmma::fill_fragment(acc[i][j], 0.0f);

    const int nstage = DHID / 32;
    for (int kt = 0; kt < nstage; kt++) {
        const int k0 = kt * 32;
#pragma unroll
        for (int i = 0; i < 4; i++) {
            float4 v = avalid[i] ? *(const float4*)(aptr[i] + k0)
                                 : make_float4(0.f, 0.f, 0.f, 0.f);
            *(float4*)&As[arow[i] * AS_STRIDE + ak4[i]] = v;
        }
#pragma unroll
        for (int i = 0; i < 4; i++) {
            float4 v = *(const float4*)(Wbase + (size_t)(k0 + bk[i]) * DIM + bn4[i]);
            *(float4*)&Bs[bk[i] * BS_STRIDE + bn4[i]] = v;
        }
        __syncthreads();

#pragma unroll
        for (int kk = 0; kk < 4; kk++) {
            FragA a[4];
            FragB b[2];
#pragma unroll
            for (int fm = 0; fm < 4; fm++) {
                wmma::load_matrix_sync(a[fm], &As[(wm * 64 + fm * 16) * AS_STRIDE + kk * 8], AS_STRIDE);
#pragma unroll
                for (int t = 0; t < a[fm].num_elements; t++)
                    a[fm].x[t] = wmma::__float_to_tf32(a[fm].x[t]);
            }
#pragma unroll
            for (int fn = 0; fn < 2; fn++) {
                wmma::load_matrix_sync(b[fn], &Bs[(kk * 8) * BS_STRIDE + wn * 32 + fn * 16], BS_STRIDE);
#pragma unroll
                for (int t = 0; t < b[fn].num_elements; t++)
                    b[fn].x[t] = wmma::__float_to_tf32(b[fn].x[t]);
            }
#pragma unroll
            for (int fm = 0; fm < 4; fm++)
#pragma unroll
                for (int fn = 0; fn < 2; fn++)
                    wmma::mma_sync(acc[fm][fn], a[fm], b[fn], acc[fm][fn]);
        }
        __syncthreads();
    }

    // epilogue scalars
    const float s_a = sigmoidf_(shifta[0]);
    const float s_b = sigmoidf_(shiftb[0]);
    const float cf  = 0.5f * (s_a + s_b);   // multiplies sigmoid(scales)*f
    const float cy  = 0.5f * (s_b - s_a);   // multiplies y

    float* cbuf = &Cs[wid * 256];
    const float* b2e = b2 + (size_t)e * DIM;
#pragma unroll
    for (int fm = 0; fm < 4; fm++) {
#pragma unroll
        for (int fn = 0; fn < 2; fn++) {
            wmma::store_matrix_sync(cbuf, acc[fm][fn], 16, wmma::mem_row_major);
            __syncwarp();
#pragma unroll
            for (int j = 0; j < 8; j++) {
                int idx = lane + j * 32;
                int r = idx >> 4, c = idx & 15;
                int gm   = tm * 128 + wm * 64 + fm * 16 + r;
                int gcol = tn * 128 + wn * 32 + fn * 16 + c;
                if (gm < cnt) {
                    int orow = g_perm[seg0 + gm];
                    float f = cbuf[idx] + b2e[gcol];
                    f = sigmoidf_(scales[gcol]) * f;
                    out[(size_t)orow * DIM + gcol] = cf * f + cy * y[(size_t)orow * DIM + gcol];
                }
            }
            __syncwarp();
        }
    }
}

// ---------------- launch ----------------
extern "C" void kernel_launch(void* const* d_in, const int* in_sizes, int n_in,
                              void* d_out, int out_size)
{
    const float* t      = (const float*)d_in[0];
    const float* y      = (const float*)d_in[1];
    const float* W1     = (const float*)d_in[2];
    const float* b1     = (const float*)d_in[3];
    const float* W2     = (const float*)d_in[4];
    const float* b2     = (const float*)d_in[5];
    const float* scales = (const float*)d_in[6];
    const float* shifta = (const float*)d_in[7];
    const float* shiftb = (const float*)d_in[8];
    float* out = (float*)d_out;

    k_zero<<<1, 32>>>();
    k_hist<<<(BATCH + 255) / 256, 256>>>(t);
    k_scan<<<1, 1>>>();
    k_scatter<<<(BATCH + 255) / 256, 256>>>(t);

    dim3 g1(DHID / 128, BATCH / 128, NUM_E);
    k_gemm1<<<g1, 256>>>(y, W1, b1);

    dim3 g2(DIM / 128, BATCH / 128, NUM_E);
    k_gemm2<<<g2, 256>>>(y, W2, b2, scales, shifta, shiftb, out);
}